// round 1
// baseline (speedup 1.0000x reference)
#include <cuda_runtime.h>
#include <math.h>

// Problem constants (fixed by the dataset)
#define NNODES 102400
#define NEDGES 409600
#define ETOT   (NEDGES + NNODES)   // edges + self loops
#define HC 256
#define NH 4
#define CD 64
#define RM_MAX 4096
#define RHID 512

// ---------------- scratch (device globals; no allocation allowed) ----------
__device__ float g_h[(size_t)NNODES * HC];    // transformed features (x @ W)
__device__ float g_o[(size_t)NNODES * HC];    // aggregated output
__device__ float g_als[NNODES * NH];
__device__ float g_ald[NNODES * NH];
__device__ float g_m[NNODES * NH];
__device__ float g_s[NNODES * NH];
__device__ float g_e[(size_t)ETOT * NH];
__device__ float g_r1[RM_MAX * RHID];
__device__ float g_r2[RM_MAX * RHID];
__device__ int   g_is32;

// ---------------- helpers ----------------
__device__ __forceinline__ void atomicMaxFloat(float* addr, float val) {
    if (val >= 0.f) atomicMax((int*)addr, __float_as_int(val));
    else            atomicMin((unsigned int*)addr, __float_as_uint(val));
}

__device__ __forceinline__ void load_edge(const void* ei, int is32, int idx,
                                          int& src, int& dst) {
    if (idx < NEDGES) {
        if (is32) {
            src = ((const int*)ei)[idx];
            dst = ((const int*)ei)[NEDGES + idx];
        } else {
            src = (int)((const long long*)ei)[idx];
            dst = (int)((const long long*)ei)[NEDGES + idx];
        }
    } else {
        src = dst = idx - NEDGES;   // self loop
    }
}

// ---------------- index dtype detection ----------------
// Interpret the first NEDGES 8-byte words of edge_index. If the data is truly
// int64, every value is in [0, NNODES). If it is int32, most words combine two
// indices and land far outside that range.
__global__ void detect_idx_kernel(const long long* ei, int* flag) {
    int i = blockIdx.x * blockDim.x + threadIdx.x;
    if (i >= NEDGES) return;
    long long v = ei[i];
    if (v < 0 || v >= (long long)NNODES) atomicOr(flag, 1);
}

// ---------------- generic SGEMM: C = A[MxK] @ B[KxN] (+bias) (+leaky 0.01) --
#define BM 64
#define BN 64
#define BK 16
__global__ void gemm_bias_act(const float* __restrict__ A, const float* __restrict__ B,
                              const float* __restrict__ bias, float* __restrict__ C,
                              int M, int N, int K, int act)
{
    __shared__ float As[BK][BM];
    __shared__ float Bs[BK][BN];
    int tid = threadIdx.x;
    int tx = tid & 15, ty = tid >> 4;
    int rowBase = blockIdx.y * BM;
    int colBase = blockIdx.x * BN;
    float acc[4][4] = {};
    int aRow = tid >> 2;          // 0..63
    int aCol = (tid & 3) * 4;     // 0,4,8,12
    int bRow = tid >> 4;          // 0..15
    int bCol = (tid & 15) * 4;    // 0..60

    for (int k0 = 0; k0 < K; k0 += BK) {
#pragma unroll
        for (int j = 0; j < 4; j++) {
            int r = rowBase + aRow, kk = k0 + aCol + j;
            As[aCol + j][aRow] = (r < M && kk < K) ? A[(size_t)r * K + kk] : 0.f;
        }
#pragma unroll
        for (int j = 0; j < 4; j++) {
            int kk = k0 + bRow, c = colBase + bCol + j;
            Bs[bRow][bCol + j] = (kk < K && c < N) ? B[(size_t)kk * N + c] : 0.f;
        }
        __syncthreads();
#pragma unroll
        for (int k = 0; k < BK; k++) {
            float a[4], b[4];
#pragma unroll
            for (int i = 0; i < 4; i++) a[i] = As[k][ty * 4 + i];
#pragma unroll
            for (int j = 0; j < 4; j++) b[j] = Bs[k][tx * 4 + j];
#pragma unroll
            for (int i = 0; i < 4; i++)
#pragma unroll
                for (int j = 0; j < 4; j++)
                    acc[i][j] += a[i] * b[j];
        }
        __syncthreads();
    }
#pragma unroll
    for (int i = 0; i < 4; i++) {
        int r = rowBase + ty * 4 + i;
        if (r >= M) continue;
#pragma unroll
        for (int j = 0; j < 4; j++) {
            int c = colBase + tx * 4 + j;
            if (c >= N) continue;
            float v = acc[i][j] + (bias ? bias[c] : 0.f);
            if (act) v = v > 0.f ? v : 0.01f * v;
            C[(size_t)r * N + c] = v;
        }
    }
}

// ---------------- per-node attention logits + segment-state init -----------
__global__ void node_al_kernel(const float* __restrict__ feat,
                               const float* __restrict__ a_src,
                               const float* __restrict__ a_dst,
                               float* __restrict__ als, float* __restrict__ ald,
                               float* __restrict__ m, float* __restrict__ s)
{
    int i = blockIdx.x * blockDim.x + threadIdx.x;
    if (i >= NNODES * NH) return;
    int n = i >> 2, h = i & 3;
    const float4* f  = (const float4*)(feat + (size_t)n * HC + h * CD);
    const float4* a4 = (const float4*)(a_src + h * CD);
    const float4* d4 = (const float4*)(a_dst + h * CD);
    float s1 = 0.f, s2 = 0.f;
#pragma unroll
    for (int k = 0; k < CD / 4; k++) {
        float4 fv = f[k], av = a4[k], dv = d4[k];
        s1 += fv.x * av.x + fv.y * av.y + fv.z * av.z + fv.w * av.w;
        s2 += fv.x * dv.x + fv.y * dv.y + fv.z * dv.z + fv.w * dv.w;
    }
    als[i] = s1;
    ald[i] = s2;
    m[i] = -3.402823466e38f;
    s[i] = 0.f;
}

// ---------------- edge pass 1: e + segment max ----------------
__global__ void edge_pass1_kernel(const void* __restrict__ ei, const int* __restrict__ flag,
                                  const float4* __restrict__ als, const float4* __restrict__ ald,
                                  float4* __restrict__ ebuf, float* __restrict__ m)
{
    int idx = blockIdx.x * blockDim.x + threadIdx.x;
    if (idx >= ETOT) return;
    int is32 = *flag;
    int src, dst;
    load_edge(ei, is32, idx, src, dst);
    float4 a = als[src];
    float4 b = ald[dst];
    float4 e;
    e.x = a.x + b.x; e.x = e.x > 0.f ? e.x : 0.2f * e.x;
    e.y = a.y + b.y; e.y = e.y > 0.f ? e.y : 0.2f * e.y;
    e.z = a.z + b.z; e.z = e.z > 0.f ? e.z : 0.2f * e.z;
    e.w = a.w + b.w; e.w = e.w > 0.f ? e.w : 0.2f * e.w;
    ebuf[idx] = e;
    atomicMaxFloat(&m[dst * 4 + 0], e.x);
    atomicMaxFloat(&m[dst * 4 + 1], e.y);
    atomicMaxFloat(&m[dst * 4 + 2], e.z);
    atomicMaxFloat(&m[dst * 4 + 3], e.w);
}

// ---------------- edge pass 2: p, segment sum, weighted scatter ------------
// One warp per edge; lane l handles channels l, l+32, ..., l+224.
__global__ void edge_pass2_kernel(const void* __restrict__ ei, const int* __restrict__ flag,
                                  const float4* __restrict__ ebuf, const float4* __restrict__ m4,
                                  float* __restrict__ s,
                                  const float* __restrict__ feat, float* __restrict__ out)
{
    int gtid = blockIdx.x * blockDim.x + threadIdx.x;
    int widx = gtid >> 5;
    int lane = gtid & 31;
    if (widx >= ETOT) return;
    int is32 = *flag;
    int src, dst;
    load_edge(ei, is32, widx, src, dst);
    float4 e  = ebuf[widx];
    float4 mv = m4[dst];
    float p0 = __expf(e.x - mv.x);
    float p1 = __expf(e.y - mv.y);
    float p2 = __expf(e.z - mv.z);
    float p3 = __expf(e.w - mv.w);
    if (lane == 0) {
        atomicAdd(&s[dst * 4 + 0], p0);
        atomicAdd(&s[dst * 4 + 1], p1);
        atomicAdd(&s[dst * 4 + 2], p2);
        atomicAdd(&s[dst * 4 + 3], p3);
    }
    const float* hf = feat + (size_t)src * HC;
    float* op = out + (size_t)dst * HC;
    float pv[8] = {p0, p0, p1, p1, p2, p2, p3, p3};
#pragma unroll
    for (int i = 0; i < 8; i++) {
        int c = lane + (i << 5);
        atomicAdd(op + c, hf[c] * pv[i]);
    }
}

// ---------------- finalize: divide by s, add bias, optional leaky ----------
__global__ void finalize_kernel(float* __restrict__ out, const float* __restrict__ s,
                                const float* __restrict__ bias, int act)
{
    int i = blockIdx.x * blockDim.x + threadIdx.x;
    if (i >= NNODES * HC) return;
    int n = i >> 8;
    int c = i & 255;
    int h = c >> 6;
    float v = out[i] / s[n * 4 + h] + bias[c];
    if (act) v = v > 0.f ? v : 0.01f * v;
    out[i] = v;
}

// ---------------- host orchestration ----------------
static void launch_gemm(const float* A, const float* B, const float* bias,
                        float* C, int M, int N, int K, int act) {
    dim3 grid((N + BN - 1) / BN, (M + BM - 1) / BM);
    gemm_bias_act<<<grid, 256>>>(A, B, bias, C, M, N, K, act);
}

extern "C" void kernel_launch(void* const* d_in, const int* in_sizes, int n_in,
                              void* d_out, int out_size)
{
    const float* x    = (const float*)d_in[0];
    const void*  ei   = d_in[1];
    const float* root = (const float*)d_in[2];
    const float* W[3]  = {(const float*)d_in[3], (const float*)d_in[7],  (const float*)d_in[11]};
    const float* aS[3] = {(const float*)d_in[4], (const float*)d_in[8],  (const float*)d_in[12]};
    const float* aD[3] = {(const float*)d_in[5], (const float*)d_in[9],  (const float*)d_in[13]};
    const float* bb[3] = {(const float*)d_in[6], (const float*)d_in[10], (const float*)d_in[14]};
    const float* fc_w = (const float*)d_in[15];
    const float* fc_b = (const float*)d_in[16];
    const float* r_w1 = (const float*)d_in[17];
    const float* r_b1 = (const float*)d_in[18];
    const float* r_w2 = (const float*)d_in[19];
    const float* r_b2 = (const float*)d_in[20];
    const float* r_w3 = (const float*)d_in[21];
    const float* r_b3 = (const float*)d_in[22];

    float *p_h, *p_o, *p_als, *p_ald, *p_m, *p_s, *p_e, *p_r1, *p_r2;
    int* p_flag;
    cudaGetSymbolAddress((void**)&p_h,   g_h);
    cudaGetSymbolAddress((void**)&p_o,   g_o);
    cudaGetSymbolAddress((void**)&p_als, g_als);
    cudaGetSymbolAddress((void**)&p_ald, g_ald);
    cudaGetSymbolAddress((void**)&p_m,   g_m);
    cudaGetSymbolAddress((void**)&p_s,   g_s);
    cudaGetSymbolAddress((void**)&p_e,   g_e);
    cudaGetSymbolAddress((void**)&p_r1,  g_r1);
    cudaGetSymbolAddress((void**)&p_r2,  g_r2);
    cudaGetSymbolAddress((void**)&p_flag, g_is32);

    // Detect whether edge_index materialized as int32 or int64.
    cudaMemsetAsync(p_flag, 0, sizeof(int));
    detect_idx_kernel<<<(NEDGES + 255) / 256, 256>>>((const long long*)ei, p_flag);

    const int Fin[3] = {80, HC, HC};
    const float* layer_in = x;
    for (int L = 0; L < 3; L++) {
        // h = in @ W
        launch_gemm(layer_in, W[L], nullptr, p_h, NNODES, HC, Fin[L], 0);
        // attention logits + init m/s
        node_al_kernel<<<(NNODES * NH + 255) / 256, 256>>>(p_h, aS[L], aD[L],
                                                           p_als, p_ald, p_m, p_s);
        cudaMemsetAsync(p_o, 0, (size_t)NNODES * HC * sizeof(float));
        edge_pass1_kernel<<<(ETOT + 255) / 256, 256>>>(ei, p_flag,
                                                       (const float4*)p_als,
                                                       (const float4*)p_ald,
                                                       (float4*)p_e, p_m);
        {
            long long threads = (long long)ETOT * 32;
            int blocks = (int)((threads + 255) / 256);
            edge_pass2_kernel<<<blocks, 256>>>(ei, p_flag,
                                               (const float4*)p_e, (const float4*)p_m,
                                               p_s, p_h, p_o);
        }
        int act = (L < 2) ? 1 : 0;
        finalize_kernel<<<(NNODES * HC + 255) / 256, 256>>>(p_o, p_s, bb[L], act);
        layer_in = p_o;
    }

    // rot = h @ fc_w + fc_b  -> first NNODES*80 of d_out
    float* rot = (float*)d_out;
    launch_gemm(p_o, fc_w, fc_b, rot, NNODES, 80, HC, 0);

    // root MLP -> remaining 4096*60 of d_out
    int RM = in_sizes[2] / 60;
    float* root_out = rot + (size_t)NNODES * 80;
    launch_gemm(root, r_w1, r_b1, p_r1, RM, RHID, 60, 1);
    launch_gemm(p_r1, r_w2, r_b2, p_r2, RM, RHID, RHID, 1);
    launch_gemm(p_r2, r_w3, r_b3, root_out, RM, 60, RHID, 0);
}

// round 2
// speedup vs baseline: 1.0568x; 1.0568x over previous
#include <cuda_runtime.h>
#include <math.h>

// Problem constants (fixed by the dataset)
#define NNODES 102400
#define NEDGES 409600
#define ETOT   (NEDGES + NNODES)   // edges + self loops
#define HC 256
#define NH 4
#define CD 64
#define RM_MAX 4096
#define RHID 512

// ---------------- scratch (device globals; no allocation allowed) ----------
__device__ float g_h[(size_t)NNODES * HC];    // transformed features (x @ W)
__device__ float g_o[(size_t)NNODES * HC];    // aggregated output
__device__ float g_als[NNODES * NH];
__device__ float g_ald[NNODES * NH];
__device__ float g_m[NNODES * NH];
__device__ float g_s[NNODES * NH];
__device__ float g_e[(size_t)ETOT * NH];
__device__ float g_r1[RM_MAX * RHID];
__device__ float g_r2[RM_MAX * RHID];
__device__ int   g_is32;

// ---------------- helpers ----------------
__device__ __forceinline__ void atomicMaxFloat(float* addr, float val) {
    if (val >= 0.f) atomicMax((int*)addr, __float_as_int(val));
    else            atomicMin((unsigned int*)addr, __float_as_uint(val));
}

__device__ __forceinline__ void red_add_v4(float* addr, float a, float b, float c, float d) {
    asm volatile("red.global.add.v4.f32 [%0], {%1,%2,%3,%4};"
                 :: "l"(addr), "f"(a), "f"(b), "f"(c), "f"(d) : "memory");
}

__device__ __forceinline__ void load_edge(const void* ei, int is32, int idx,
                                          int& src, int& dst) {
    if (idx < NEDGES) {
        if (is32) {
            src = ((const int*)ei)[idx];
            dst = ((const int*)ei)[NEDGES + idx];
        } else {
            src = (int)((const long long*)ei)[idx];
            dst = (int)((const long long*)ei)[NEDGES + idx];
        }
    } else {
        src = dst = idx - NEDGES;   // self loop
    }
}

// ---------------- index dtype detection ----------------
__global__ void detect_idx_kernel(const long long* ei, int* flag) {
    int i = blockIdx.x * blockDim.x + threadIdx.x;
    if (i >= NEDGES) return;
    long long v = ei[i];
    if (v < 0 || v >= (long long)NNODES) atomicOr(flag, 1);
}

// ---------------- fast SGEMM: C = A[MxK] @ B[KxN] (+bias) (+leaky 0.01) ----
// 128x128 tile, BK=16, 256 threads, 8x8 micro-tile. Requires K%4==0, N%4==0
// for vector loads fast path (all call sites satisfy modulo handled by guards).
#define TBM 128
#define TBN 128
#define TBK 16
__global__ __launch_bounds__(256, 2)
void gemm_fast(const float* __restrict__ A, const float* __restrict__ B,
               const float* __restrict__ bias, float* __restrict__ C,
               int M, int N, int K, int act)
{
    __shared__ float As[TBK][TBM];
    __shared__ float Bs[TBK][TBN];
    int t = threadIdx.x;
    int rowBase = blockIdx.y * TBM;
    int colBase = blockIdx.x * TBN;
    int tx = t & 15, ty = t >> 4;
    float acc[8][8] = {};

    int aRow = t >> 2;          // 0..63
    int aCol = (t & 3) * 4;     // 0,4,8,12
    int bRow = t >> 5;          // 0..7
    int bCol = (t & 31) * 4;    // 0..124

    for (int k0 = 0; k0 < K; k0 += TBK) {
        // A tile: 128 rows x 16 cols, float4 along K, transposed into smem
#pragma unroll
        for (int rr = 0; rr < 2; rr++) {
            int r = rowBase + aRow + rr * 64;
            int kk = k0 + aCol;
            float4 v = make_float4(0.f, 0.f, 0.f, 0.f);
            if (r < M) {
                if (kk + 3 < K) {
                    v = *(const float4*)(A + (size_t)r * K + kk);
                } else {
                    float tmp[4];
#pragma unroll
                    for (int q = 0; q < 4; q++)
                        tmp[q] = (kk + q < K) ? A[(size_t)r * K + kk + q] : 0.f;
                    v = make_float4(tmp[0], tmp[1], tmp[2], tmp[3]);
                }
            }
            As[aCol + 0][aRow + rr * 64] = v.x;
            As[aCol + 1][aRow + rr * 64] = v.y;
            As[aCol + 2][aRow + rr * 64] = v.z;
            As[aCol + 3][aRow + rr * 64] = v.w;
        }
        // B tile: 16 rows x 128 cols, float4 along N
#pragma unroll
        for (int rr = 0; rr < 2; rr++) {
            int kk = k0 + bRow + rr * 8;
            int c = colBase + bCol;
            float4 v = make_float4(0.f, 0.f, 0.f, 0.f);
            if (kk < K) {
                if (c + 3 < N) {
                    v = *(const float4*)(B + (size_t)kk * N + c);
                } else {
                    float tmp[4];
#pragma unroll
                    for (int q = 0; q < 4; q++)
                        tmp[q] = (c + q < N) ? B[(size_t)kk * N + c + q] : 0.f;
                    v = make_float4(tmp[0], tmp[1], tmp[2], tmp[3]);
                }
            }
            *(float4*)&Bs[bRow + rr * 8][bCol] = v;
        }
        __syncthreads();
#pragma unroll
        for (int k = 0; k < TBK; k++) {
            float a[8], b[8];
            *(float4*)&a[0] = *(const float4*)&As[k][ty * 8 + 0];
            *(float4*)&a[4] = *(const float4*)&As[k][ty * 8 + 4];
            *(float4*)&b[0] = *(const float4*)&Bs[k][tx * 8 + 0];
            *(float4*)&b[4] = *(const float4*)&Bs[k][tx * 8 + 4];
#pragma unroll
            for (int i = 0; i < 8; i++)
#pragma unroll
                for (int j = 0; j < 8; j++)
                    acc[i][j] += a[i] * b[j];
        }
        __syncthreads();
    }
#pragma unroll
    for (int i = 0; i < 8; i++) {
        int r = rowBase + ty * 8 + i;
        if (r >= M) continue;
#pragma unroll
        for (int j = 0; j < 8; j++) {
            int c = colBase + tx * 8 + j;
            if (c >= N) continue;
            float v = acc[i][j] + (bias ? bias[c] : 0.f);
            if (act) v = v > 0.f ? v : 0.01f * v;
            C[(size_t)r * N + c] = v;
        }
    }
}

// ---------------- per-node attention logits + segment-state init -----------
__global__ void node_al_kernel(const float* __restrict__ feat,
                               const float* __restrict__ a_src,
                               const float* __restrict__ a_dst,
                               float* __restrict__ als, float* __restrict__ ald,
                               float* __restrict__ m, float* __restrict__ s)
{
    int i = blockIdx.x * blockDim.x + threadIdx.x;
    if (i >= NNODES * NH) return;
    int n = i >> 2, h = i & 3;
    const float4* f  = (const float4*)(feat + (size_t)n * HC + h * CD);
    const float4* a4 = (const float4*)(a_src + h * CD);
    const float4* d4 = (const float4*)(a_dst + h * CD);
    float s1 = 0.f, s2 = 0.f;
#pragma unroll
    for (int k = 0; k < CD / 4; k++) {
        float4 fv = f[k], av = a4[k], dv = d4[k];
        s1 += fv.x * av.x + fv.y * av.y + fv.z * av.z + fv.w * av.w;
        s2 += fv.x * dv.x + fv.y * dv.y + fv.z * dv.z + fv.w * dv.w;
    }
    als[i] = s1;
    ald[i] = s2;
    m[i] = -3.402823466e38f;
    s[i] = 0.f;
}

// ---------------- edge pass 1: e + segment max ----------------
__global__ void edge_pass1_kernel(const void* __restrict__ ei, const int* __restrict__ flag,
                                  const float4* __restrict__ als, const float4* __restrict__ ald,
                                  float4* __restrict__ ebuf, float* __restrict__ m)
{
    int idx = blockIdx.x * blockDim.x + threadIdx.x;
    if (idx >= ETOT) return;
    int is32 = *flag;
    int src, dst;
    load_edge(ei, is32, idx, src, dst);
    float4 a = als[src];
    float4 b = ald[dst];
    float4 e;
    e.x = a.x + b.x; e.x = e.x > 0.f ? e.x : 0.2f * e.x;
    e.y = a.y + b.y; e.y = e.y > 0.f ? e.y : 0.2f * e.y;
    e.z = a.z + b.z; e.z = e.z > 0.f ? e.z : 0.2f * e.z;
    e.w = a.w + b.w; e.w = e.w > 0.f ? e.w : 0.2f * e.w;
    ebuf[idx] = e;
    atomicMaxFloat(&m[dst * 4 + 0], e.x);
    atomicMaxFloat(&m[dst * 4 + 1], e.y);
    atomicMaxFloat(&m[dst * 4 + 2], e.z);
    atomicMaxFloat(&m[dst * 4 + 3], e.w);
}

// ---------------- edge pass 2: p, segment sum, weighted scatter ------------
// One warp per edge; lane l handles float4 channel-chunks l and l+32.
__global__ void edge_pass2_kernel(const void* __restrict__ ei, const int* __restrict__ flag,
                                  const float4* __restrict__ ebuf, const float4* __restrict__ m4,
                                  float* __restrict__ s,
                                  const float* __restrict__ feat, float* __restrict__ out)
{
    int gtid = blockIdx.x * blockDim.x + threadIdx.x;
    int widx = gtid >> 5;
    int lane = gtid & 31;
    if (widx >= ETOT) return;
    int is32 = *flag;
    int src, dst;
    load_edge(ei, is32, widx, src, dst);
    float4 e  = ebuf[widx];
    float4 mv = m4[dst];
    float p0 = __expf(e.x - mv.x);
    float p1 = __expf(e.y - mv.y);
    float p2 = __expf(e.z - mv.z);
    float p3 = __expf(e.w - mv.w);
    if (lane == 0) red_add_v4(&s[dst * 4], p0, p1, p2, p3);

    const float4* hf = (const float4*)(feat + (size_t)src * HC);
    float* op = out + (size_t)dst * HC;
    // chunk lane   (0..31): heads 0..1 -> p0 if chunk<16 else p1
    // chunk lane+32(32..63): heads 2..3 -> p2 if chunk<48 else p3
    float pwA = (lane < 16) ? p0 : p1;
    float pwB = (lane < 16) ? p2 : p3;
    float4 vA = hf[lane];
    float4 vB = hf[lane + 32];
    red_add_v4(op + lane * 4,        vA.x * pwA, vA.y * pwA, vA.z * pwA, vA.w * pwA);
    red_add_v4(op + (lane + 32) * 4, vB.x * pwB, vB.y * pwB, vB.z * pwB, vB.w * pwB);
}

// ---------------- finalize: divide by s, add bias, optional leaky ----------
__global__ void finalize_kernel(float* __restrict__ out, const float* __restrict__ s,
                                const float* __restrict__ bias, int act)
{
    int i = blockIdx.x * blockDim.x + threadIdx.x;
    if (i >= NNODES * HC) return;
    int n = i >> 8;
    int c = i & 255;
    int h = c >> 6;
    float v = out[i] / s[n * 4 + h] + bias[c];
    if (act) v = v > 0.f ? v : 0.01f * v;
    out[i] = v;
}

// ---------------- host orchestration ----------------
static void launch_gemm(const float* A, const float* B, const float* bias,
                        float* C, int M, int N, int K, int act) {
    dim3 grid((N + TBN - 1) / TBN, (M + TBM - 1) / TBM);
    gemm_fast<<<grid, 256>>>(A, B, bias, C, M, N, K, act);
}

extern "C" void kernel_launch(void* const* d_in, const int* in_sizes, int n_in,
                              void* d_out, int out_size)
{
    const float* x    = (const float*)d_in[0];
    const void*  ei   = d_in[1];
    const float* root = (const float*)d_in[2];
    const float* W[3]  = {(const float*)d_in[3], (const float*)d_in[7],  (const float*)d_in[11]};
    const float* aS[3] = {(const float*)d_in[4], (const float*)d_in[8],  (const float*)d_in[12]};
    const float* aD[3] = {(const float*)d_in[5], (const float*)d_in[9],  (const float*)d_in[13]};
    const float* bb[3] = {(const float*)d_in[6], (const float*)d_in[10], (const float*)d_in[14]};
    const float* fc_w = (const float*)d_in[15];
    const float* fc_b = (const float*)d_in[16];
    const float* r_w1 = (const float*)d_in[17];
    const float* r_b1 = (const float*)d_in[18];
    const float* r_w2 = (const float*)d_in[19];
    const float* r_b2 = (const float*)d_in[20];
    const float* r_w3 = (const float*)d_in[21];
    const float* r_b3 = (const float*)d_in[22];

    float *p_h, *p_o, *p_als, *p_ald, *p_m, *p_s, *p_e, *p_r1, *p_r2;
    int* p_flag;
    cudaGetSymbolAddress((void**)&p_h,   g_h);
    cudaGetSymbolAddress((void**)&p_o,   g_o);
    cudaGetSymbolAddress((void**)&p_als, g_als);
    cudaGetSymbolAddress((void**)&p_ald, g_ald);
    cudaGetSymbolAddress((void**)&p_m,   g_m);
    cudaGetSymbolAddress((void**)&p_s,   g_s);
    cudaGetSymbolAddress((void**)&p_e,   g_e);
    cudaGetSymbolAddress((void**)&p_r1,  g_r1);
    cudaGetSymbolAddress((void**)&p_r2,  g_r2);
    cudaGetSymbolAddress((void**)&p_flag, g_is32);

    // Detect whether edge_index materialized as int32 or int64.
    cudaMemsetAsync(p_flag, 0, sizeof(int));
    detect_idx_kernel<<<(NEDGES + 255) / 256, 256>>>((const long long*)ei, p_flag);

    const int Fin[3] = {80, HC, HC};
    const float* layer_in = x;
    for (int L = 0; L < 3; L++) {
        launch_gemm(layer_in, W[L], nullptr, p_h, NNODES, HC, Fin[L], 0);
        node_al_kernel<<<(NNODES * NH + 255) / 256, 256>>>(p_h, aS[L], aD[L],
                                                           p_als, p_ald, p_m, p_s);
        cudaMemsetAsync(p_o, 0, (size_t)NNODES * HC * sizeof(float));
        edge_pass1_kernel<<<(ETOT + 255) / 256, 256>>>(ei, p_flag,
                                                       (const float4*)p_als,
                                                       (const float4*)p_ald,
                                                       (float4*)p_e, p_m);
        {
            long long threads = (long long)ETOT * 32;
            int blocks = (int)((threads + 255) / 256);
            edge_pass2_kernel<<<blocks, 256>>>(ei, p_flag,
                                               (const float4*)p_e, (const float4*)p_m,
                                               p_s, p_h, p_o);
        }
        int act = (L < 2) ? 1 : 0;
        finalize_kernel<<<(NNODES * HC + 255) / 256, 256>>>(p_o, p_s, bb[L], act);
        layer_in = p_o;
    }

    // rot = h @ fc_w + fc_b  -> first NNODES*80 of d_out
    float* rot = (float*)d_out;
    launch_gemm(p_o, fc_w, fc_b, rot, NNODES, 80, HC, 0);

    // root MLP -> remaining 4096*60 of d_out
    int RM = in_sizes[2] / 60;
    float* root_out = rot + (size_t)NNODES * 80;
    launch_gemm(root, r_w1, r_b1, p_r1, RM, RHID, 60, 1);
    launch_gemm(p_r1, r_w2, r_b2, p_r2, RM, RHID, RHID, 1);
    launch_gemm(p_r2, r_w3, r_b3, root_out, RM, 60, RHID, 0);
}

// round 4
// speedup vs baseline: 1.7645x; 1.6696x over previous
#include <cuda_runtime.h>
#include <cuda_bf16.h>
#include <cstdint>
#include <math.h>

// Problem constants (fixed by the dataset)
#define NNODES 102400
#define NEDGES 409600
#define ETOT   (NEDGES + NNODES)   // edges + self loops
#define HC 256
#define NH 4
#define CD 64

// ======================= small helpers =====================================
__device__ __forceinline__ uint32_t smem_to_u32(const void* p) {
    uint32_t a;
    asm("{ .reg .u64 t; cvta.to.shared.u64 t, %1; cvt.u32.u64 %0, t; }" : "=r"(a) : "l"(p));
    return a;
}
__device__ __forceinline__ void cp16(uint32_t s, const void* g) {
    asm volatile("cp.async.cg.shared.global [%0], [%1], 16;" :: "r"(s), "l"(g));
}
__device__ __forceinline__ uint32_t lds32(uint32_t a) {
    uint32_t v; asm volatile("ld.shared.b32 %0, [%1];" : "=r"(v) : "r"(a)); return v;
}
// smem byte address of b32 column c (0..31) in 128B row r, XOR-swizzled per 16B granule
__device__ __forceinline__ uint32_t smaddr(uint32_t base, int r, int c) {
    return base + r * 128 + ((((c >> 2) ^ (r & 7)) << 4)) + ((c & 3) << 2);
}
__device__ __forceinline__ void mma_bf16(float* d, uint32_t a0, uint32_t a1, uint32_t a2,
                                         uint32_t a3, uint32_t b0, uint32_t b1) {
    asm volatile(
        "mma.sync.aligned.m16n8k16.row.col.f32.bf16.bf16.f32 "
        "{%0,%1,%2,%3}, {%4,%5,%6,%7}, {%8,%9}, {%0,%1,%2,%3};"
        : "+f"(d[0]), "+f"(d[1]), "+f"(d[2]), "+f"(d[3])
        : "r"(a0), "r"(a1), "r"(a2), "r"(a3), "r"(b0), "r"(b1));
}

// ======================= scratch (device globals) ==========================
__device__ __align__(16) float g_h[(size_t)NNODES * HC];
__device__ __align__(16) float g_o[(size_t)NNODES * HC];
__device__ __align__(16) float g_als[NNODES * NH];
__device__ __align__(16) float g_ald[NNODES * NH];
__device__ __align__(16) float g_m[NNODES * NH];
__device__ __align__(16) float g_s[NNODES * NH];
__device__ __align__(16) float g_e[(size_t)ETOT * NH];
__device__ int g_is32;
// bf16-split operands
__device__ __align__(16) __nv_bfloat16 g_Ahi[(size_t)NNODES * HC];
__device__ __align__(16) __nv_bfloat16 g_Alo[(size_t)NNODES * HC];
__device__ __align__(16) __nv_bfloat16 g_Bhi[660000];
__device__ __align__(16) __nv_bfloat16 g_Blo[660000];
__device__ __align__(16) __nv_bfloat16 g_rAh[4096 * 64];
__device__ __align__(16) __nv_bfloat16 g_rAl[4096 * 64];
__device__ __align__(16) __nv_bfloat16 g_r1h[4096 * 512];
__device__ __align__(16) __nv_bfloat16 g_r1l[4096 * 512];
__device__ __align__(16) __nv_bfloat16 g_r2h[4096 * 512];
__device__ __align__(16) __nv_bfloat16 g_r2l[4096 * 512];

// B buffer element offsets (B stored [Npad][Kpad], hi/lo, zero padded)
#define OFF_W0  0        // 256 x 128
#define OFF_W1  32768    // 256 x 256
#define OFF_W2  98304    // 256 x 256
#define OFF_FC  163840   // 256 x 256
#define OFF_R1  229376   // 512 x 64
#define OFF_R2  262144   // 512 x 512
#define OFF_R3  524288   // 256 x 512

// ======================= misc small kernels ================================
__global__ void detect_idx_kernel(const long long* ei, int* flag) {
    int i = blockIdx.x * blockDim.x + threadIdx.x;
    if (i >= NEDGES) return;
    long long v = ei[i];
    if (v < 0 || v >= (long long)NNODES) atomicOr(flag, 1);
}

__global__ void conv_A_kernel(const float* __restrict__ A,
                              __nv_bfloat16* __restrict__ hi, __nv_bfloat16* __restrict__ lo,
                              int M, int K, int Kpad) {
    int i = blockIdx.x * blockDim.x + threadIdx.x;
    if (i >= M * Kpad) return;
    int m = i / Kpad, k = i - m * Kpad;
    float v = (k < K) ? A[(size_t)m * K + k] : 0.f;
    __nv_bfloat16 h16 = __float2bfloat16(v);
    hi[i] = h16;
    lo[i] = __float2bfloat16(v - __bfloat162float(h16));
}

// B [K,N] fp32 row-major -> Bt [Npad, Kpad] bf16 hi/lo (zero padded)
__global__ void conv_B_kernel(const float* __restrict__ B,
                              __nv_bfloat16* __restrict__ hi, __nv_bfloat16* __restrict__ lo,
                              int K, int N, int Kpad, int Npad) {
    int i = blockIdx.x * blockDim.x + threadIdx.x;
    if (i >= Npad * Kpad) return;
    int n = i / Kpad, k = i - n * Kpad;
    float v = (k < K && n < N) ? B[(size_t)k * N + n] : 0.f;
    __nv_bfloat16 h16 = __float2bfloat16(v);
    hi[i] = h16;
    lo[i] = __float2bfloat16(v - __bfloat162float(h16));
}

// ======================= bf16-split mma.sync GEMM ==========================
// C[M, Ntot] = A @ B^T.  A: hi/lo bf16 [M, Kpad] row-major.  B: hi/lo bf16
// [Npad, Kpad] (row n holds column n of the math B).  CTA tile 128x256,
// 512 threads = 4x4 warps, warp tile 32 rows x 64 cols. KB=64 double buffer.
// Epilogues: fp32 out (+bias,+act), bf16 hi/lo out (+bias,+act), fused GAT
// attention logits (a_src != null; requires gridDim.y == 1, cols = 256).
#define SM_STAGE 98304   // 96KB per stage: Ahi 16K | Alo 16K | Bhi 32K | Blo 32K
__global__ __launch_bounds__(512, 1)
void gemm_mma(const __nv_bfloat16* __restrict__ Ahi, const __nv_bfloat16* __restrict__ Alo,
              int Kpad,
              const __nv_bfloat16* __restrict__ Bhi, const __nv_bfloat16* __restrict__ Blo,
              float* outf, int nwrite, int ldout,
              __nv_bfloat16* ohi, __nv_bfloat16* olo, int ldo2,
              const float* __restrict__ bias, int act,
              const float* __restrict__ a_src, const float* __restrict__ a_dst,
              float* als, float* ald, float* minit, float* sinit)
{
    extern __shared__ char sm_raw[];
    uint32_t sb = smem_to_u32(sm_raw);
    int tid = threadIdx.x, wid = tid >> 5, lane = tid & 31;
    int warpM = wid & 3, warpN = wid >> 2;
    int mBase = blockIdx.x * 128;
    int nBase = blockIdx.y * 256;
    const int NC = Kpad >> 6;
    const int kp = lane & 3;
    const int lq = lane >> 2;

    float acc[2][8][4];
#pragma unroll
    for (int i = 0; i < 2; i++)
#pragma unroll
        for (int j = 0; j < 8; j++)
#pragma unroll
            for (int q = 0; q < 4; q++) acc[i][j][q] = 0.f;

    // ---- prologue: load chunk 0 into stage 0 ----
    {
        uint32_t base = sb;
#pragma unroll
        for (int i = 0; i < 4; i++) {                 // A: 2048 granules
            int u = tid + i * 512;
            int hl = u >> 10, rem = u & 1023, row = rem >> 3, g = rem & 7;
            const __nv_bfloat16* src = (hl ? Alo : Ahi) + (size_t)(mBase + row) * Kpad + g * 8;
            cp16(base + hl * 16384 + row * 128 + (((g ^ (row & 7)) << 4)), src);
        }
#pragma unroll
        for (int i = 0; i < 8; i++) {                 // B: 4096 granules
            int u = tid + i * 512;
            int hl = u >> 11, rem = u & 2047, row = rem >> 3, g = rem & 7;
            const __nv_bfloat16* src = (hl ? Blo : Bhi) + (size_t)(nBase + row) * Kpad + g * 8;
            cp16(base + 32768 + hl * 32768 + row * 128 + (((g ^ (row & 7)) << 4)), src);
        }
        asm volatile("cp.async.commit_group;" ::: "memory");
    }

    for (int c = 0; c < NC; c++) {
        if (c + 1 < NC) {        // prefetch next chunk into other stage
            uint32_t base = sb + ((c + 1) & 1) * SM_STAGE;
            int ko = (c + 1) * 64;
#pragma unroll
            for (int i = 0; i < 4; i++) {
                int u = tid + i * 512;
                int hl = u >> 10, rem = u & 1023, row = rem >> 3, g = rem & 7;
                const __nv_bfloat16* src = (hl ? Alo : Ahi) + (size_t)(mBase + row) * Kpad + ko + g * 8;
                cp16(base + hl * 16384 + row * 128 + (((g ^ (row & 7)) << 4)), src);
            }
#pragma unroll
            for (int i = 0; i < 8; i++) {
                int u = tid + i * 512;
                int hl = u >> 11, rem = u & 2047, row = rem >> 3, g = rem & 7;
                const __nv_bfloat16* src = (hl ? Blo : Bhi) + (size_t)(nBase + row) * Kpad + ko + g * 8;
                cp16(base + 32768 + hl * 32768 + row * 128 + (((g ^ (row & 7)) << 4)), src);
            }
            asm volatile("cp.async.commit_group;" ::: "memory");
            asm volatile("cp.async.wait_group 1;" ::: "memory");
        } else {
            asm volatile("cp.async.wait_group 0;" ::: "memory");
        }
        __syncthreads();

        uint32_t aB = sb + (c & 1) * SM_STAGE;
        uint32_t bB = aB + 32768;
#pragma unroll
        for (int k16 = 0; k16 < 4; k16++) {
            int c0 = k16 * 8;
            uint32_t Ah[2][4], Al[2][4];
#pragma unroll
            for (int mf = 0; mf < 2; mf++) {
                int r0 = warpM * 32 + mf * 16 + lq;
                Ah[mf][0] = lds32(smaddr(aB, r0,     c0 + kp));
                Ah[mf][1] = lds32(smaddr(aB, r0 + 8, c0 + kp));
                Ah[mf][2] = lds32(smaddr(aB, r0,     c0 + kp + 4));
                Ah[mf][3] = lds32(smaddr(aB, r0 + 8, c0 + kp + 4));
                Al[mf][0] = lds32(smaddr(aB + 16384, r0,     c0 + kp));
                Al[mf][1] = lds32(smaddr(aB + 16384, r0 + 8, c0 + kp));
                Al[mf][2] = lds32(smaddr(aB + 16384, r0,     c0 + kp + 4));
                Al[mf][3] = lds32(smaddr(aB + 16384, r0 + 8, c0 + kp + 4));
            }
#pragma unroll
            for (int n8 = 0; n8 < 8; n8++) {
                int n = warpN * 64 + n8 * 8 + lq;
                uint32_t bh0 = lds32(smaddr(bB, n, c0 + kp));
                uint32_t bh1 = lds32(smaddr(bB, n, c0 + kp + 4));
                uint32_t bl0 = lds32(smaddr(bB + 32768, n, c0 + kp));
                uint32_t bl1 = lds32(smaddr(bB + 32768, n, c0 + kp + 4));
#pragma unroll
                for (int mf = 0; mf < 2; mf++) {
                    mma_bf16(acc[mf][n8], Ah[mf][0], Ah[mf][1], Ah[mf][2], Ah[mf][3], bh0, bh1);
                    mma_bf16(acc[mf][n8], Ah[mf][0], Ah[mf][1], Ah[mf][2], Ah[mf][3], bl0, bl1);
                    mma_bf16(acc[mf][n8], Al[mf][0], Al[mf][1], Al[mf][2], Al[mf][3], bh0, bh1);
                }
            }
        }
        __syncthreads();
    }

    // ---- epilogue ----
    int limit = nwrite - nBase;                 // valid cols in this CTA block
    float s1[2][2] = {{0.f, 0.f}, {0.f, 0.f}};
    float s2[2][2] = {{0.f, 0.f}, {0.f, 0.f}};
#pragma unroll
    for (int mf = 0; mf < 2; mf++) {
        int gr0 = mBase + warpM * 32 + mf * 16 + lq;
#pragma unroll
        for (int n8 = 0; n8 < 8; n8++) {
            int cl = warpN * 64 + n8 * 8 + kp * 2;     // col within 256-block
            float v[4];
#pragma unroll
            for (int q = 0; q < 4; q++) v[q] = acc[mf][n8][q];
            // bias + act (guarded by valid col)
#pragma unroll
            for (int q = 0; q < 4; q++) {
                int col = cl + (q & 1);
                if (col < limit) {
                    float x = v[q];
                    if (bias) x += bias[nBase + col];
                    if (act) x = x > 0.f ? x : 0.01f * x;
                    v[q] = x;
                }
            }
            if (a_src) {   // fused attention logits (raw h values; bias/act off here)
                s1[mf][0] += v[0] * a_src[cl] + v[1] * a_src[cl + 1];
                s2[mf][0] += v[0] * a_dst[cl] + v[1] * a_dst[cl + 1];
                s1[mf][1] += v[2] * a_src[cl] + v[3] * a_src[cl + 1];
                s2[mf][1] += v[2] * a_dst[cl] + v[3] * a_dst[cl + 1];
            }
            if (outf) {
                if (cl + 1 < limit) {
                    *(float2*)(outf + (size_t)gr0 * ldout + nBase + cl) = make_float2(v[0], v[1]);
                    *(float2*)(outf + (size_t)(gr0 + 8) * ldout + nBase + cl) = make_float2(v[2], v[3]);
                } else if (cl < limit) {
                    outf[(size_t)gr0 * ldout + nBase + cl] = v[0];
                    outf[(size_t)(gr0 + 8) * ldout + nBase + cl] = v[2];
                }
            }
            if (ohi && cl + 1 < limit + 1) {  // root MLP widths are even & full
                if (cl < limit) {
                    __nv_bfloat16 h0 = __float2bfloat16(v[0]);
                    __nv_bfloat16 h1 = __float2bfloat16(v[1]);
                    __nv_bfloat16 l0 = __float2bfloat16(v[0] - __bfloat162float(h0));
                    __nv_bfloat16 l1 = __float2bfloat16(v[1] - __bfloat162float(h1));
                    *(__nv_bfloat162*)(ohi + (size_t)gr0 * ldo2 + nBase + cl) = __nv_bfloat162(h0, h1);
                    *(__nv_bfloat162*)(olo + (size_t)gr0 * ldo2 + nBase + cl) = __nv_bfloat162(l0, l1);
                    __nv_bfloat16 h2 = __float2bfloat16(v[2]);
                    __nv_bfloat16 h3 = __float2bfloat16(v[3]);
                    __nv_bfloat16 l2 = __float2bfloat16(v[2] - __bfloat162float(h2));
                    __nv_bfloat16 l3 = __float2bfloat16(v[3] - __bfloat162float(h3));
                    *(__nv_bfloat162*)(ohi + (size_t)(gr0 + 8) * ldo2 + nBase + cl) = __nv_bfloat162(h2, h3);
                    *(__nv_bfloat162*)(olo + (size_t)(gr0 + 8) * ldo2 + nBase + cl) = __nv_bfloat162(l2, l3);
                }
            }
        }
    }
    if (a_src) {
        // reduce across the 4 lanes covering the same rows (lane%4 group)
#pragma unroll
        for (int mf = 0; mf < 2; mf++)
#pragma unroll
            for (int hf = 0; hf < 2; hf++) {
                s1[mf][hf] += __shfl_xor_sync(0xFFFFFFFF, s1[mf][hf], 1);
                s1[mf][hf] += __shfl_xor_sync(0xFFFFFFFF, s1[mf][hf], 2);
                s2[mf][hf] += __shfl_xor_sync(0xFFFFFFFF, s2[mf][hf], 1);
                s2[mf][hf] += __shfl_xor_sync(0xFFFFFFFF, s2[mf][hf], 2);
            }
        if ((lane & 3) == 0) {
#pragma unroll
            for (int mf = 0; mf < 2; mf++)
#pragma unroll
                for (int hf = 0; hf < 2; hf++) {
                    int gr = mBase + warpM * 32 + mf * 16 + hf * 8 + lq;
                    als[gr * 4 + warpN] = s1[mf][hf];
                    ald[gr * 4 + warpN] = s2[mf][hf];
                    minit[gr * 4 + warpN] = -3.402823466e38f;
                    sinit[gr * 4 + warpN] = 0.f;
                }
        }
    }
}

// ======================= edge kernels ======================================
__device__ __forceinline__ void atomicMaxFloat(float* addr, float val) {
    if (val >= 0.f) atomicMax((int*)addr, __float_as_int(val));
    else            atomicMin((unsigned int*)addr, __float_as_uint(val));
}
__device__ __forceinline__ void red_add_v4(float* addr, float a, float b, float c, float d) {
    asm volatile("red.global.add.v4.f32 [%0], {%1,%2,%3,%4};"
                 :: "l"(addr), "f"(a), "f"(b), "f"(c), "f"(d) : "memory");
}
__device__ __forceinline__ void load_edge(const void* ei, int is32, int idx,
                                          int& src, int& dst) {
    if (idx < NEDGES) {
        if (is32) {
            src = ((const int*)ei)[idx];
            dst = ((const int*)ei)[NEDGES + idx];
        } else {
            src = (int)((const long long*)ei)[idx];
            dst = (int)((const long long*)ei)[NEDGES + idx];
        }
    } else {
        src = dst = idx - NEDGES;
    }
}

__global__ void edge_pass1_kernel(const void* __restrict__ ei, const int* __restrict__ flag,
                                  const float4* __restrict__ als, const float4* __restrict__ ald,
                                  float4* __restrict__ ebuf, float* __restrict__ m)
{
    int idx = blockIdx.x * blockDim.x + threadIdx.x;
    if (idx >= ETOT) return;
    int is32 = *flag;
    int src, dst;
    load_edge(ei, is32, idx, src, dst);
    float4 a = als[src];
    float4 b = ald[dst];
    float4 e;
    e.x = a.x + b.x; e.x = e.x > 0.f ? e.x : 0.2f * e.x;
    e.y = a.y + b.y; e.y = e.y > 0.f ? e.y : 0.2f * e.y;
    e.z = a.z + b.z; e.z = e.z > 0.f ? e.z : 0.2f * e.z;
    e.w = a.w + b.w; e.w = e.w > 0.f ? e.w : 0.2f * e.w;
    ebuf[idx] = e;
    atomicMaxFloat(&m[dst * 4 + 0], e.x);
    atomicMaxFloat(&m[dst * 4 + 1], e.y);
    atomicMaxFloat(&m[dst * 4 + 2], e.z);
    atomicMaxFloat(&m[dst * 4 + 3], e.w);
}

__global__ void edge_pass2_kernel(const void* __restrict__ ei, const int* __restrict__ flag,
                                  const float4* __restrict__ ebuf, const float4* __restrict__ m4,
                                  float* __restrict__ s,
                                  const float* __restrict__ feat, float* __restrict__ out)
{
    int gtid = blockIdx.x * blockDim.x + threadIdx.x;
    int widx = gtid >> 5;
    int lane = gtid & 31;
    if (widx >= ETOT) return;
    int is32 = *flag;
    int src, dst;
    load_edge(ei, is32, widx, src, dst);
    float4 e  = ebuf[widx];
    float4 mv = m4[dst];
    float p0 = __expf(e.x - mv.x);
    float p1 = __expf(e.y - mv.y);
    float p2 = __expf(e.z - mv.z);
    float p3 = __expf(e.w - mv.w);
    if (lane == 0) red_add_v4(&s[dst * 4], p0, p1, p2, p3);

    const float4* hf = (const float4*)(feat + (size_t)src * HC);
    float* op = out + (size_t)dst * HC;
    float pwA = (lane < 16) ? p0 : p1;
    float pwB = (lane < 16) ? p2 : p3;
    float4 vA = hf[lane];
    float4 vB = hf[lane + 32];
    red_add_v4(op + lane * 4,        vA.x * pwA, vA.y * pwA, vA.z * pwA, vA.w * pwA);
    red_add_v4(op + (lane + 32) * 4, vB.x * pwB, vB.y * pwB, vB.z * pwB, vB.w * pwB);
}

// finalize: v = acc/s + bias (+leaky) -> write bf16 hi/lo (next GEMM's A)
__global__ void finalize_hilo_kernel(const float* __restrict__ acc, const float* __restrict__ s,
                                     const float* __restrict__ bias, int act,
                                     __nv_bfloat16* __restrict__ hi, __nv_bfloat16* __restrict__ lo)
{
    int i = blockIdx.x * blockDim.x + threadIdx.x;
    if (i >= NNODES * HC) return;
    int n = i >> 8;
    int c = i & 255;
    int h = c >> 6;
    float v = acc[i] / s[n * 4 + h] + bias[c];
    if (act) v = v > 0.f ? v : 0.01f * v;
    __nv_bfloat16 h16 = __float2bfloat16(v);
    hi[i] = h16;
    lo[i] = __float2bfloat16(v - __bfloat162float(h16));
}

// ======================= host orchestration ================================
#define GEMM_SMEM (2 * SM_STAGE)

extern "C" void kernel_launch(void* const* d_in, const int* in_sizes, int n_in,
                              void* d_out, int out_size)
{
    const float* x    = (const float*)d_in[0];
    const void*  ei   = d_in[1];
    const float* root = (const float*)d_in[2];
    const float* W[3]  = {(const float*)d_in[3], (const float*)d_in[7],  (const float*)d_in[11]};
    const float* aS[3] = {(const float*)d_in[4], (const float*)d_in[8],  (const float*)d_in[12]};
    const float* aD[3] = {(const float*)d_in[5], (const float*)d_in[9],  (const float*)d_in[13]};
    const float* bb[3] = {(const float*)d_in[6], (const float*)d_in[10], (const float*)d_in[14]};
    const float* fc_w = (const float*)d_in[15];
    const float* fc_b = (const float*)d_in[16];
    const float* r_w1 = (const float*)d_in[17];
    const float* r_b1 = (const float*)d_in[18];
    const float* r_w2 = (const float*)d_in[19];
    const float* r_b2 = (const float*)d_in[20];
    const float* r_w3 = (const float*)d_in[21];
    const float* r_b3 = (const float*)d_in[22];

    float *p_h, *p_o, *p_als, *p_ald, *p_m, *p_s, *p_e;
    int* p_flag;
    __nv_bfloat16 *p_Ahi, *p_Alo, *p_Bhi, *p_Blo, *p_rAh, *p_rAl, *p_r1h, *p_r1l, *p_r2h, *p_r2l;
    cudaGetSymbolAddress((void**)&p_h,   g_h);
    cudaGetSymbolAddress((void**)&p_o,   g_o);
    cudaGetSymbolAddress((void**)&p_als, g_als);
    cudaGetSymbolAddress((void**)&p_ald, g_ald);
    cudaGetSymbolAddress((void**)&p_m,   g_m);
    cudaGetSymbolAddress((void**)&p_s,   g_s);
    cudaGetSymbolAddress((void**)&p_e,   g_e);
    cudaGetSymbolAddress((void**)&p_flag, g_is32);
    cudaGetSymbolAddress((void**)&p_Ahi, g_Ahi);
    cudaGetSymbolAddress((void**)&p_Alo, g_Alo);
    cudaGetSymbolAddress((void**)&p_Bhi, g_Bhi);
    cudaGetSymbolAddress((void**)&p_Blo, g_Blo);
    cudaGetSymbolAddress((void**)&p_rAh, g_rAh);
    cudaGetSymbolAddress((void**)&p_rAl, g_rAl);
    cudaGetSymbolAddress((void**)&p_r1h, g_r1h);
    cudaGetSymbolAddress((void**)&p_r1l, g_r1l);
    cudaGetSymbolAddress((void**)&p_r2h, g_r2h);
    cudaGetSymbolAddress((void**)&p_r2l, g_r2l);

    static int smem_set = 0;
    if (!smem_set) {
        cudaFuncSetAttribute(gemm_mma, cudaFuncAttributeMaxDynamicSharedMemorySize, GEMM_SMEM);
        smem_set = 1;
    }

    // edge-index dtype detection
    cudaMemsetAsync(p_flag, 0, sizeof(int));
    detect_idx_kernel<<<(NEDGES + 255) / 256, 256>>>((const long long*)ei, p_flag);

    // weight conversions (B^T hi/lo, zero padded)
    conv_B_kernel<<<(256 * 128 + 255) / 256, 256>>>(W[0], p_Bhi + OFF_W0, p_Blo + OFF_W0, 80, 256, 128, 256);
    conv_B_kernel<<<(256 * 256 + 255) / 256, 256>>>(W[1], p_Bhi + OFF_W1, p_Blo + OFF_W1, 256, 256, 256, 256);
    conv_B_kernel<<<(256 * 256 + 255) / 256, 256>>>(W[2], p_Bhi + OFF_W2, p_Blo + OFF_W2, 256, 256, 256, 256);
    conv_B_kernel<<<(256 * 256 + 255) / 256, 256>>>(fc_w, p_Bhi + OFF_FC, p_Blo + OFF_FC, 256, 80, 256, 256);
    conv_B_kernel<<<(512 * 64 + 255) / 256, 256>>>(r_w1, p_Bhi + OFF_R1, p_Blo + OFF_R1, 60, 512, 64, 512);
    conv_B_kernel<<<(512 * 512 + 255) / 256, 256>>>(r_w2, p_Bhi + OFF_R2, p_Blo + OFF_R2, 512, 512, 512, 512);
    conv_B_kernel<<<(256 * 512 + 255) / 256, 256>>>(r_w3, p_Bhi + OFF_R3, p_Blo + OFF_R3, 512, 60, 512, 256);

    // x -> bf16 hi/lo, K padded 80->128
    conv_A_kernel<<<(NNODES * 128 + 255) / 256, 256>>>(x, p_Ahi, p_Alo, NNODES, 80, 128);

    const int Kpad[3] = {128, 256, 256};
    const __nv_bfloat16* Boff_hi[3] = {p_Bhi + OFF_W0, p_Bhi + OFF_W1, p_Bhi + OFF_W2};
    const __nv_bfloat16* Boff_lo[3] = {p_Blo + OFF_W0, p_Blo + OFF_W1, p_Blo + OFF_W2};

    for (int L = 0; L < 3; L++) {
        // h = A @ W  (epilogue: write fp32 h + al_s/al_d + init m/s)
        gemm_mma<<<dim3(NNODES / 128, 1), 512, GEMM_SMEM>>>(
            p_Ahi, p_Alo, Kpad[L], Boff_hi[L], Boff_lo[L],
            p_h, 256, 256, nullptr, nullptr, 0,
            nullptr, 0, aS[L], aD[L], p_als, p_ald, p_m, p_s);
        cudaMemsetAsync(p_o, 0, (size_t)NNODES * HC * sizeof(float));
        edge_pass1_kernel<<<(ETOT + 255) / 256, 256>>>(ei, p_flag,
                                                       (const float4*)p_als, (const float4*)p_ald,
                                                       (float4*)p_e, p_m);
        {
            long long threads = (long long)ETOT * 32;
            int blocks = (int)((threads + 255) / 256);
            edge_pass2_kernel<<<blocks, 256>>>(ei, p_flag,
                                               (const float4*)p_e, (const float4*)p_m,
                                               p_s, p_h, p_o);
        }
        int act = (L < 2) ? 1 : 0;
        finalize_hilo_kernel<<<(NNODES * HC + 255) / 256, 256>>>(p_o, p_s, bb[L], act,
                                                                 p_Ahi, p_Alo);
    }

    // rot = h @ fc_w + fc_b -> d_out[0 : N*80]
    float* rot = (float*)d_out;
    gemm_mma<<<dim3(NNODES / 128, 1), 512, GEMM_SMEM>>>(
        p_Ahi, p_Alo, 256, p_Bhi + OFF_FC, p_Blo + OFF_FC,
        rot, 80, 80, nullptr, nullptr, 0,
        fc_b, 0, nullptr, nullptr, nullptr, nullptr, nullptr, nullptr);

    // root MLP
    conv_A_kernel<<<(4096 * 64 + 255) / 256, 256>>>(root, p_rAh, p_rAl, 4096, 60, 64);
    gemm_mma<<<dim3(32, 2), 512, GEMM_SMEM>>>(
        p_rAh, p_rAl, 64, p_Bhi + OFF_R1, p_Blo + OFF_R1,
        nullptr, 512, 0, p_r1h, p_r1l, 512,
        r_b1, 1, nullptr, nullptr, nullptr, nullptr, nullptr, nullptr);
    gemm_mma<<<dim3(32, 2), 512, GEMM_SMEM>>>(
        p_r1h, p_r1l, 512, p_Bhi + OFF_R2, p_Blo + OFF_R2,
        nullptr, 512, 0, p_r2h, p_r2l, 512,
        r_b2, 1, nullptr, nullptr, nullptr, nullptr, nullptr, nullptr);
    float* root_out = rot + (size_t)NNODES * 80;
    gemm_mma<<<dim3(32, 1), 512, GEMM_SMEM>>>(
        p_r2h, p_r2l, 512, p_Bhi + OFF_R3, p_Blo + OFF_R3,
        root_out, 60, 60, nullptr, nullptr, 0,
        r_b3, 0, nullptr, nullptr, nullptr, nullptr, nullptr, nullptr);
}

// round 5
// speedup vs baseline: 2.1424x; 1.2142x over previous
#include <cuda_runtime.h>
#include <cuda_bf16.h>
#include <cstdint>
#include <math.h>

// Problem constants (fixed by the dataset)
#define NNODES 102400
#define NEDGES 409600
#define HC 256
#define NH 4

// ======================= small helpers =====================================
__device__ __forceinline__ uint32_t smem_to_u32(const void* p) {
    uint32_t a;
    asm("{ .reg .u64 t; cvta.to.shared.u64 t, %1; cvt.u32.u64 %0, t; }" : "=r"(a) : "l"(p));
    return a;
}
__device__ __forceinline__ void cp16(uint32_t s, const void* g) {
    asm volatile("cp.async.cg.shared.global [%0], [%1], 16;" :: "r"(s), "l"(g));
}
__device__ __forceinline__ uint32_t lds32(uint32_t a) {
    uint32_t v; asm volatile("ld.shared.b32 %0, [%1];" : "=r"(v) : "r"(a)); return v;
}
__device__ __forceinline__ uint32_t smaddr(uint32_t base, int r, int c) {
    return base + r * 128 + ((((c >> 2) ^ (r & 7)) << 4)) + ((c & 3) << 2);
}
__device__ __forceinline__ void mma_bf16(float* d, uint32_t a0, uint32_t a1, uint32_t a2,
                                         uint32_t a3, uint32_t b0, uint32_t b1) {
    asm volatile(
        "mma.sync.aligned.m16n8k16.row.col.f32.bf16.bf16.f32 "
        "{%0,%1,%2,%3}, {%4,%5,%6,%7}, {%8,%9}, {%0,%1,%2,%3};"
        : "+f"(d[0]), "+f"(d[1]), "+f"(d[2]), "+f"(d[3])
        : "r"(a0), "r"(a1), "r"(a2), "r"(a3), "r"(b0), "r"(b1));
}
__device__ __forceinline__ float4 leaky4_02(float4 v) {
    v.x = v.x > 0.f ? v.x : 0.2f * v.x;
    v.y = v.y > 0.f ? v.y : 0.2f * v.y;
    v.z = v.z > 0.f ? v.z : 0.2f * v.z;
    v.w = v.w > 0.f ? v.w : 0.2f * v.w;
    return v;
}

// ======================= scratch (device globals) ==========================
__device__ __align__(16) float g_h[(size_t)NNODES * HC];
__device__ __align__(16) float g_als[NNODES * NH];
__device__ __align__(16) float g_ald[NNODES * NH];
__device__ int g_off[NNODES + 1];
__device__ int g_cur[NNODES];
__device__ int g_srcarr[NEDGES];
__device__ int g_is32;
// bf16-split operands
__device__ __align__(16) __nv_bfloat16 g_Ahi[(size_t)NNODES * HC];
__device__ __align__(16) __nv_bfloat16 g_Alo[(size_t)NNODES * HC];
__device__ __align__(16) __nv_bfloat16 g_Bhi[660000];
__device__ __align__(16) __nv_bfloat16 g_Blo[660000];
__device__ __align__(16) __nv_bfloat16 g_rAh[4096 * 64];
__device__ __align__(16) __nv_bfloat16 g_rAl[4096 * 64];
__device__ __align__(16) __nv_bfloat16 g_r1h[4096 * 512];
__device__ __align__(16) __nv_bfloat16 g_r1l[4096 * 512];
__device__ __align__(16) __nv_bfloat16 g_r2h[4096 * 512];
__device__ __align__(16) __nv_bfloat16 g_r2l[4096 * 512];

// B buffer element offsets (B stored [Npad][Kpad], hi/lo, zero padded)
#define OFF_W0  0        // 256 x 128
#define OFF_W1  32768    // 256 x 256
#define OFF_W2  98304    // 256 x 256
#define OFF_FC  163840   // 256 x 256
#define OFF_R1  229376   // 512 x 64
#define OFF_R2  262144   // 512 x 512
#define OFF_R3  524288   // 256 x 512

// ======================= edge utilities ====================================
__device__ __forceinline__ void load_edge(const void* ei, int is32, int idx,
                                          int& src, int& dst) {
    if (is32) {
        src = ((const int*)ei)[idx];
        dst = ((const int*)ei)[NEDGES + idx];
    } else {
        src = (int)((const long long*)ei)[idx];
        dst = (int)((const long long*)ei)[NEDGES + idx];
    }
}

__global__ void detect_idx_kernel(const long long* ei, int* flag) {
    int i = blockIdx.x * blockDim.x + threadIdx.x;
    if (i >= NEDGES) return;
    long long v = ei[i];
    if (v < 0 || v >= (long long)NNODES) atomicOr(flag, 1);
}

__global__ void hist_kernel(const void* __restrict__ ei, const int* __restrict__ flag,
                            int* __restrict__ counts) {
    int i = blockIdx.x * blockDim.x + threadIdx.x;
    if (i >= NEDGES) return;
    int s, d;
    load_edge(ei, *flag, i, s, d);
    atomicAdd(&counts[d], 1);
}

// single block, 1024 threads, 100 counts each (1024*100 == NNODES)
__global__ void scan_kernel(int* __restrict__ counts_cursor, int* __restrict__ offs) {
    __shared__ int part[1024];
    int t = threadIdx.x;
    int base = t * 100;
    int sum = 0;
    for (int i = 0; i < 100; i++) sum += counts_cursor[base + i];
    part[t] = sum;
    __syncthreads();
    for (int d = 1; d < 1024; d <<= 1) {
        int v = (t >= d) ? part[t - d] : 0;
        __syncthreads();
        part[t] += v;
        __syncthreads();
    }
    int run = (t == 0) ? 0 : part[t - 1];
    for (int i = 0; i < 100; i++) {
        int c = counts_cursor[base + i];
        offs[base + i] = run;
        counts_cursor[base + i] = run;   // cursor for scatter
        run += c;
    }
    if (t == 1023) offs[NNODES] = run;
}

__global__ void scatter_kernel(const void* __restrict__ ei, const int* __restrict__ flag,
                               int* __restrict__ cursor, int* __restrict__ srcarr) {
    int i = blockIdx.x * blockDim.x + threadIdx.x;
    if (i >= NEDGES) return;
    int s, d;
    load_edge(ei, *flag, i, s, d);
    int pos = atomicAdd(&cursor[d], 1);
    srcarr[pos] = s;
}

// ======================= misc conversions ==================================
__global__ void conv_A_kernel(const float* __restrict__ A,
                              __nv_bfloat16* __restrict__ hi, __nv_bfloat16* __restrict__ lo,
                              int M, int K, int Kpad) {
    int i = blockIdx.x * blockDim.x + threadIdx.x;
    if (i >= M * Kpad) return;
    int m = i / Kpad, k = i - m * Kpad;
    float v = (k < K) ? A[(size_t)m * K + k] : 0.f;
    __nv_bfloat16 h16 = __float2bfloat16(v);
    hi[i] = h16;
    lo[i] = __float2bfloat16(v - __bfloat162float(h16));
}

__global__ void conv_B_kernel(const float* __restrict__ B,
                              __nv_bfloat16* __restrict__ hi, __nv_bfloat16* __restrict__ lo,
                              int K, int N, int Kpad, int Npad) {
    int i = blockIdx.x * blockDim.x + threadIdx.x;
    if (i >= Npad * Kpad) return;
    int n = i / Kpad, k = i - n * Kpad;
    float v = (k < K && n < N) ? B[(size_t)k * N + n] : 0.f;
    __nv_bfloat16 h16 = __float2bfloat16(v);
    hi[i] = h16;
    lo[i] = __float2bfloat16(v - __bfloat162float(h16));
}

// ======================= bf16-split mma.sync GEMM ==========================
#define SM_STAGE 98304
__global__ __launch_bounds__(512, 1)
void gemm_mma(const __nv_bfloat16* __restrict__ Ahi, const __nv_bfloat16* __restrict__ Alo,
              int Kpad,
              const __nv_bfloat16* __restrict__ Bhi, const __nv_bfloat16* __restrict__ Blo,
              float* outf, int nwrite, int ldout,
              __nv_bfloat16* ohi, __nv_bfloat16* olo, int ldo2,
              const float* __restrict__ bias, int act,
              const float* __restrict__ a_src, const float* __restrict__ a_dst,
              float* als, float* ald)
{
    extern __shared__ char sm_raw[];
    uint32_t sb = smem_to_u32(sm_raw);
    int tid = threadIdx.x, wid = tid >> 5, lane = tid & 31;
    int warpM = wid & 3, warpN = wid >> 2;
    int mBase = blockIdx.x * 128;
    int nBase = blockIdx.y * 256;
    const int NC = Kpad >> 6;
    const int kp = lane & 3;
    const int lq = lane >> 2;

    float acc[2][8][4];
#pragma unroll
    for (int i = 0; i < 2; i++)
#pragma unroll
        for (int j = 0; j < 8; j++)
#pragma unroll
            for (int q = 0; q < 4; q++) acc[i][j][q] = 0.f;

    {
        uint32_t base = sb;
#pragma unroll
        for (int i = 0; i < 4; i++) {
            int u = tid + i * 512;
            int hl = u >> 10, rem = u & 1023, row = rem >> 3, g = rem & 7;
            const __nv_bfloat16* src = (hl ? Alo : Ahi) + (size_t)(mBase + row) * Kpad + g * 8;
            cp16(base + hl * 16384 + row * 128 + (((g ^ (row & 7)) << 4)), src);
        }
#pragma unroll
        for (int i = 0; i < 8; i++) {
            int u = tid + i * 512;
            int hl = u >> 11, rem = u & 2047, row = rem >> 3, g = rem & 7;
            const __nv_bfloat16* src = (hl ? Blo : Bhi) + (size_t)(nBase + row) * Kpad + g * 8;
            cp16(base + 32768 + hl * 32768 + row * 128 + (((g ^ (row & 7)) << 4)), src);
        }
        asm volatile("cp.async.commit_group;" ::: "memory");
    }

    for (int c = 0; c < NC; c++) {
        if (c + 1 < NC) {
            uint32_t base = sb + ((c + 1) & 1) * SM_STAGE;
            int ko = (c + 1) * 64;
#pragma unroll
            for (int i = 0; i < 4; i++) {
                int u = tid + i * 512;
                int hl = u >> 10, rem = u & 1023, row = rem >> 3, g = rem & 7;
                const __nv_bfloat16* src = (hl ? Alo : Ahi) + (size_t)(mBase + row) * Kpad + ko + g * 8;
                cp16(base + hl * 16384 + row * 128 + (((g ^ (row & 7)) << 4)), src);
            }
#pragma unroll
            for (int i = 0; i < 8; i++) {
                int u = tid + i * 512;
                int hl = u >> 11, rem = u & 2047, row = rem >> 3, g = rem & 7;
                const __nv_bfloat16* src = (hl ? Blo : Bhi) + (size_t)(nBase + row) * Kpad + ko + g * 8;
                cp16(base + 32768 + hl * 32768 + row * 128 + (((g ^ (row & 7)) << 4)), src);
            }
            asm volatile("cp.async.commit_group;" ::: "memory");
            asm volatile("cp.async.wait_group 1;" ::: "memory");
        } else {
            asm volatile("cp.async.wait_group 0;" ::: "memory");
        }
        __syncthreads();

        uint32_t aB = sb + (c & 1) * SM_STAGE;
        uint32_t bB = aB + 32768;
#pragma unroll
        for (int k16 = 0; k16 < 4; k16++) {
            int c0 = k16 * 8;
            uint32_t Ah[2][4], Al[2][4];
#pragma unroll
            for (int mf = 0; mf < 2; mf++) {
                int r0 = warpM * 32 + mf * 16 + lq;
                Ah[mf][0] = lds32(smaddr(aB, r0,     c0 + kp));
                Ah[mf][1] = lds32(smaddr(aB, r0 + 8, c0 + kp));
                Ah[mf][2] = lds32(smaddr(aB, r0,     c0 + kp + 4));
                Ah[mf][3] = lds32(smaddr(aB, r0 + 8, c0 + kp + 4));
                Al[mf][0] = lds32(smaddr(aB + 16384, r0,     c0 + kp));
                Al[mf][1] = lds32(smaddr(aB + 16384, r0 + 8, c0 + kp));
                Al[mf][2] = lds32(smaddr(aB + 16384, r0,     c0 + kp + 4));
                Al[mf][3] = lds32(smaddr(aB + 16384, r0 + 8, c0 + kp + 4));
            }
#pragma unroll
            for (int n8 = 0; n8 < 8; n8++) {
                int n = warpN * 64 + n8 * 8 + lq;
                uint32_t bh0 = lds32(smaddr(bB, n, c0 + kp));
                uint32_t bh1 = lds32(smaddr(bB, n, c0 + kp + 4));
                uint32_t bl0 = lds32(smaddr(bB + 32768, n, c0 + kp));
                uint32_t bl1 = lds32(smaddr(bB + 32768, n, c0 + kp + 4));
#pragma unroll
                for (int mf = 0; mf < 2; mf++) {
                    mma_bf16(acc[mf][n8], Ah[mf][0], Ah[mf][1], Ah[mf][2], Ah[mf][3], bh0, bh1);
                    mma_bf16(acc[mf][n8], Ah[mf][0], Ah[mf][1], Ah[mf][2], Ah[mf][3], bl0, bl1);
                    mma_bf16(acc[mf][n8], Al[mf][0], Al[mf][1], Al[mf][2], Al[mf][3], bh0, bh1);
                }
            }
        }
        __syncthreads();
    }

    // ---- epilogue ----
    int limit = nwrite - nBase;
    float s1[2][2] = {{0.f, 0.f}, {0.f, 0.f}};
    float s2[2][2] = {{0.f, 0.f}, {0.f, 0.f}};
#pragma unroll
    for (int mf = 0; mf < 2; mf++) {
        int gr0 = mBase + warpM * 32 + mf * 16 + lq;
#pragma unroll
        for (int n8 = 0; n8 < 8; n8++) {
            int cl = warpN * 64 + n8 * 8 + kp * 2;
            float v[4];
#pragma unroll
            for (int q = 0; q < 4; q++) v[q] = acc[mf][n8][q];
#pragma unroll
            for (int q = 0; q < 4; q++) {
                int col = cl + (q & 1);
                if (col < limit) {
                    float x = v[q];
                    if (bias) x += bias[nBase + col];
                    if (act) x = x > 0.f ? x : 0.01f * x;
                    v[q] = x;
                }
            }
            if (a_src) {
                s1[mf][0] += v[0] * a_src[cl] + v[1] * a_src[cl + 1];
                s2[mf][0] += v[0] * a_dst[cl] + v[1] * a_dst[cl + 1];
                s1[mf][1] += v[2] * a_src[cl] + v[3] * a_src[cl + 1];
                s2[mf][1] += v[2] * a_dst[cl] + v[3] * a_dst[cl + 1];
            }
            if (outf) {
                if (cl + 1 < limit) {
                    *(float2*)(outf + (size_t)gr0 * ldout + nBase + cl) = make_float2(v[0], v[1]);
                    *(float2*)(outf + (size_t)(gr0 + 8) * ldout + nBase + cl) = make_float2(v[2], v[3]);
                } else if (cl < limit) {
                    outf[(size_t)gr0 * ldout + nBase + cl] = v[0];
                    outf[(size_t)(gr0 + 8) * ldout + nBase + cl] = v[2];
                }
            }
            if (ohi && cl < limit) {
                __nv_bfloat16 h0 = __float2bfloat16(v[0]);
                __nv_bfloat16 h1 = __float2bfloat16(v[1]);
                __nv_bfloat16 l0 = __float2bfloat16(v[0] - __bfloat162float(h0));
                __nv_bfloat16 l1 = __float2bfloat16(v[1] - __bfloat162float(h1));
                *(__nv_bfloat162*)(ohi + (size_t)gr0 * ldo2 + nBase + cl) = __nv_bfloat162(h0, h1);
                *(__nv_bfloat162*)(olo + (size_t)gr0 * ldo2 + nBase + cl) = __nv_bfloat162(l0, l1);
                __nv_bfloat16 h2 = __float2bfloat16(v[2]);
                __nv_bfloat16 h3 = __float2bfloat16(v[3]);
                __nv_bfloat16 l2 = __float2bfloat16(v[2] - __bfloat162float(h2));
                __nv_bfloat16 l3 = __float2bfloat16(v[3] - __bfloat162float(h3));
                *(__nv_bfloat162*)(ohi + (size_t)(gr0 + 8) * ldo2 + nBase + cl) = __nv_bfloat162(h2, h3);
                *(__nv_bfloat162*)(olo + (size_t)(gr0 + 8) * ldo2 + nBase + cl) = __nv_bfloat162(l2, l3);
            }
        }
    }
    if (a_src) {
#pragma unroll
        for (int mf = 0; mf < 2; mf++)
#pragma unroll
            for (int hf = 0; hf < 2; hf++) {
                s1[mf][hf] += __shfl_xor_sync(0xFFFFFFFF, s1[mf][hf], 1);
                s1[mf][hf] += __shfl_xor_sync(0xFFFFFFFF, s1[mf][hf], 2);
                s2[mf][hf] += __shfl_xor_sync(0xFFFFFFFF, s2[mf][hf], 1);
                s2[mf][hf] += __shfl_xor_sync(0xFFFFFFFF, s2[mf][hf], 2);
            }
        if ((lane & 3) == 0) {
#pragma unroll
            for (int mf = 0; mf < 2; mf++)
#pragma unroll
                for (int hf = 0; hf < 2; hf++) {
                    int gr = mBase + warpM * 32 + mf * 16 + hf * 8 + lq;
                    als[gr * 4 + warpN] = s1[mf][hf];
                    ald[gr * 4 + warpN] = s2[mf][hf];
                }
        }
    }
}

// ======================= fused GAT aggregation (one warp per dst) ==========
// For dst n: m = max e over in-edges (+self), p = exp(e-m), s = sum p,
// out = (sum p*h[src]) / s + bias (+leaky) -> bf16 hi/lo for next layer.
__global__ __launch_bounds__(256)
void gat_agg(const int* __restrict__ offs, const int* __restrict__ srcarr,
             const float4* __restrict__ als4, const float4* __restrict__ ald4,
             const float* __restrict__ h,
             const float* __restrict__ bias, int act,
             __nv_bfloat16* __restrict__ ohi, __nv_bfloat16* __restrict__ olo)
{
    int w = (blockIdx.x * blockDim.x + threadIdx.x) >> 5;
    int lane = threadIdx.x & 31;
    if (w >= NNODES) return;
    int n = w;
    int beg = offs[n], end = offs[n + 1];
    float4 aldn = ald4[n];
    float4 an = als4[n];
    float4 eself = leaky4_02(make_float4(an.x + aldn.x, an.y + aldn.y,
                                         an.z + aldn.z, an.w + aldn.w));
    // ---- pass 1: segment max ----
    float4 m = eself;
    for (int j = beg + lane; j < end; j += 32) {
        int s = srcarr[j];
        float4 a = als4[s];
        float4 e = leaky4_02(make_float4(a.x + aldn.x, a.y + aldn.y,
                                         a.z + aldn.z, a.w + aldn.w));
        m.x = fmaxf(m.x, e.x); m.y = fmaxf(m.y, e.y);
        m.z = fmaxf(m.z, e.z); m.w = fmaxf(m.w, e.w);
    }
#pragma unroll
    for (int o = 16; o; o >>= 1) {
        m.x = fmaxf(m.x, __shfl_xor_sync(0xFFFFFFFF, m.x, o));
        m.y = fmaxf(m.y, __shfl_xor_sync(0xFFFFFFFF, m.y, o));
        m.z = fmaxf(m.z, __shfl_xor_sync(0xFFFFFFFF, m.z, o));
        m.w = fmaxf(m.w, __shfl_xor_sync(0xFFFFFFFF, m.w, o));
    }
    // ---- pass 2: p, sum, gather-accumulate ----
    float acc[8] = {0.f, 0.f, 0.f, 0.f, 0.f, 0.f, 0.f, 0.f};
    float4 psum = make_float4(0.f, 0.f, 0.f, 0.f);
    for (int base = beg; base < end; base += 32) {
        int j = base + lane;
        int valid = j < end;
        int s = valid ? srcarr[j] : 0;
        float4 p = make_float4(0.f, 0.f, 0.f, 0.f);
        if (valid) {
            float4 a = als4[s];
            float4 e = leaky4_02(make_float4(a.x + aldn.x, a.y + aldn.y,
                                             a.z + aldn.z, a.w + aldn.w));
            p.x = __expf(e.x - m.x); p.y = __expf(e.y - m.y);
            p.z = __expf(e.z - m.z); p.w = __expf(e.w - m.w);
            psum.x += p.x; psum.y += p.y; psum.z += p.z; psum.w += p.w;
        }
        int cnt = end - base; if (cnt > 32) cnt = 32;
        for (int jj = 0; jj < cnt; jj++) {
            int   sj = __shfl_sync(0xFFFFFFFF, s, jj);
            float px = __shfl_sync(0xFFFFFFFF, p.x, jj);
            float py = __shfl_sync(0xFFFFFFFF, p.y, jj);
            float pz = __shfl_sync(0xFFFFFFFF, p.z, jj);
            float pw = __shfl_sync(0xFFFFFFFF, p.w, jj);
            const float4* hf = (const float4*)(h + (size_t)sj * HC);
            float pA = (lane < 16) ? px : py;
            float pB = (lane < 16) ? pz : pw;
            float4 vA = __ldg(&hf[lane]);
            float4 vB = __ldg(&hf[lane + 32]);
            acc[0] += pA * vA.x; acc[1] += pA * vA.y;
            acc[2] += pA * vA.z; acc[3] += pA * vA.w;
            acc[4] += pB * vB.x; acc[5] += pB * vB.y;
            acc[6] += pB * vB.z; acc[7] += pB * vB.w;
        }
    }
#pragma unroll
    for (int o = 16; o; o >>= 1) {
        psum.x += __shfl_xor_sync(0xFFFFFFFF, psum.x, o);
        psum.y += __shfl_xor_sync(0xFFFFFFFF, psum.y, o);
        psum.z += __shfl_xor_sync(0xFFFFFFFF, psum.z, o);
        psum.w += __shfl_xor_sync(0xFFFFFFFF, psum.w, o);
    }
    // self loop contribution
    float4 ps;
    ps.x = __expf(eself.x - m.x); ps.y = __expf(eself.y - m.y);
    ps.z = __expf(eself.z - m.z); ps.w = __expf(eself.w - m.w);
    psum.x += ps.x; psum.y += ps.y; psum.z += ps.z; psum.w += ps.w;
    {
        const float4* hf = (const float4*)(h + (size_t)n * HC);
        float pA = (lane < 16) ? ps.x : ps.y;
        float pB = (lane < 16) ? ps.z : ps.w;
        float4 vA = hf[lane];
        float4 vB = hf[lane + 32];
        acc[0] += pA * vA.x; acc[1] += pA * vA.y;
        acc[2] += pA * vA.z; acc[3] += pA * vA.w;
        acc[4] += pB * vB.x; acc[5] += pB * vB.y;
        acc[6] += pB * vB.z; acc[7] += pB * vB.w;
    }
    // ---- epilogue: divide, bias, act, write bf16 hi/lo ----
    float sA = (lane < 16) ? psum.x : psum.y;
    float sB = (lane < 16) ? psum.z : psum.w;
    const float4* b4 = (const float4*)bias;
    float4 bA = b4[lane], bB = b4[lane + 32];
    float v[8];
    float rA = 1.f / sA, rB = 1.f / sB;
    v[0] = acc[0] * rA + bA.x; v[1] = acc[1] * rA + bA.y;
    v[2] = acc[2] * rA + bA.z; v[3] = acc[3] * rA + bA.w;
    v[4] = acc[4] * rB + bB.x; v[5] = acc[5] * rB + bB.y;
    v[6] = acc[6] * rB + bB.z; v[7] = acc[7] * rB + bB.w;
    if (act) {
#pragma unroll
        for (int q = 0; q < 8; q++) v[q] = v[q] > 0.f ? v[q] : 0.01f * v[q];
    }
    size_t i0 = (size_t)n * HC + lane * 4;
    size_t i1 = (size_t)n * HC + (lane + 32) * 4;
#pragma unroll
    for (int g = 0; g < 2; g++) {
        size_t ix = g ? i1 : i0;
        const float* vv = v + g * 4;
        __nv_bfloat16 h0 = __float2bfloat16(vv[0]);
        __nv_bfloat16 h1 = __float2bfloat16(vv[1]);
        __nv_bfloat16 h2 = __float2bfloat16(vv[2]);
        __nv_bfloat16 h3 = __float2bfloat16(vv[3]);
        *(__nv_bfloat162*)(ohi + ix)     = __nv_bfloat162(h0, h1);
        *(__nv_bfloat162*)(ohi + ix + 2) = __nv_bfloat162(h2, h3);
        __nv_bfloat16 l0 = __float2bfloat16(vv[0] - __bfloat162float(h0));
        __nv_bfloat16 l1 = __float2bfloat16(vv[1] - __bfloat162float(h1));
        __nv_bfloat16 l2 = __float2bfloat16(vv[2] - __bfloat162float(h2));
        __nv_bfloat16 l3 = __float2bfloat16(vv[3] - __bfloat162float(h3));
        *(__nv_bfloat162*)(olo + ix)     = __nv_bfloat162(l0, l1);
        *(__nv_bfloat162*)(olo + ix + 2) = __nv_bfloat162(l2, l3);
    }
}

// ======================= host orchestration ================================
#define GEMM_SMEM (2 * SM_STAGE)

extern "C" void kernel_launch(void* const* d_in, const int* in_sizes, int n_in,
                              void* d_out, int out_size)
{
    const float* x    = (const float*)d_in[0];
    const void*  ei   = d_in[1];
    const float* root = (const float*)d_in[2];
    const float* W[3]  = {(const float*)d_in[3], (const float*)d_in[7],  (const float*)d_in[11]};
    const float* aS[3] = {(const float*)d_in[4], (const float*)d_in[8],  (const float*)d_in[12]};
    const float* aD[3] = {(const float*)d_in[5], (const float*)d_in[9],  (const float*)d_in[13]};
    const float* bb[3] = {(const float*)d_in[6], (const float*)d_in[10], (const float*)d_in[14]};
    const float* fc_w = (const float*)d_in[15];
    const float* fc_b = (const float*)d_in[16];
    const float* r_w1 = (const float*)d_in[17];
    const float* r_b1 = (const float*)d_in[18];
    const float* r_w2 = (const float*)d_in[19];
    const float* r_b2 = (const float*)d_in[20];
    const float* r_w3 = (const float*)d_in[21];
    const float* r_b3 = (const float*)d_in[22];

    float *p_h, *p_als, *p_ald;
    int *p_off, *p_cur, *p_srcarr, *p_flag;
    __nv_bfloat16 *p_Ahi, *p_Alo, *p_Bhi, *p_Blo, *p_rAh, *p_rAl, *p_r1h, *p_r1l, *p_r2h, *p_r2l;
    cudaGetSymbolAddress((void**)&p_h,   g_h);
    cudaGetSymbolAddress((void**)&p_als, g_als);
    cudaGetSymbolAddress((void**)&p_ald, g_ald);
    cudaGetSymbolAddress((void**)&p_off, g_off);
    cudaGetSymbolAddress((void**)&p_cur, g_cur);
    cudaGetSymbolAddress((void**)&p_srcarr, g_srcarr);
    cudaGetSymbolAddress((void**)&p_flag, g_is32);
    cudaGetSymbolAddress((void**)&p_Ahi, g_Ahi);
    cudaGetSymbolAddress((void**)&p_Alo, g_Alo);
    cudaGetSymbolAddress((void**)&p_Bhi, g_Bhi);
    cudaGetSymbolAddress((void**)&p_Blo, g_Blo);
    cudaGetSymbolAddress((void**)&p_rAh, g_rAh);
    cudaGetSymbolAddress((void**)&p_rAl, g_rAl);
    cudaGetSymbolAddress((void**)&p_r1h, g_r1h);
    cudaGetSymbolAddress((void**)&p_r1l, g_r1l);
    cudaGetSymbolAddress((void**)&p_r2h, g_r2h);
    cudaGetSymbolAddress((void**)&p_r2l, g_r2l);

    static int smem_set = 0;
    if (!smem_set) {
        cudaFuncSetAttribute(gemm_mma, cudaFuncAttributeMaxDynamicSharedMemorySize, GEMM_SMEM);
        smem_set = 1;
    }

    // ---- CSR build (once per call, reused by all 3 layers) ----
    cudaMemsetAsync(p_flag, 0, sizeof(int));
    detect_idx_kernel<<<(NEDGES + 255) / 256, 256>>>((const long long*)ei, p_flag);
    cudaMemsetAsync(p_cur, 0, NNODES * sizeof(int));
    hist_kernel<<<(NEDGES + 255) / 256, 256>>>(ei, p_flag, p_cur);
    scan_kernel<<<1, 1024>>>(p_cur, p_off);
    scatter_kernel<<<(NEDGES + 255) / 256, 256>>>(ei, p_flag, p_cur, p_srcarr);

    // ---- weight conversions ----
    conv_B_kernel<<<(256 * 128 + 255) / 256, 256>>>(W[0], p_Bhi + OFF_W0, p_Blo + OFF_W0, 80, 256, 128, 256);
    conv_B_kernel<<<(256 * 256 + 255) / 256, 256>>>(W[1], p_Bhi + OFF_W1, p_Blo + OFF_W1, 256, 256, 256, 256);
    conv_B_kernel<<<(256 * 256 + 255) / 256, 256>>>(W[2], p_Bhi + OFF_W2, p_Blo + OFF_W2, 256, 256, 256, 256);
    conv_B_kernel<<<(256 * 256 + 255) / 256, 256>>>(fc_w, p_Bhi + OFF_FC, p_Blo + OFF_FC, 256, 80, 256, 256);
    conv_B_kernel<<<(512 * 64 + 255) / 256, 256>>>(r_w1, p_Bhi + OFF_R1, p_Blo + OFF_R1, 60, 512, 64, 512);
    conv_B_kernel<<<(512 * 512 + 255) / 256, 256>>>(r_w2, p_Bhi + OFF_R2, p_Blo + OFF_R2, 512, 512, 512, 512);
    conv_B_kernel<<<(256 * 512 + 255) / 256, 256>>>(r_w3, p_Bhi + OFF_R3, p_Blo + OFF_R3, 512, 60, 512, 256);

    // x -> bf16 hi/lo, K padded 80->128
    conv_A_kernel<<<(NNODES * 128 + 255) / 256, 256>>>(x, p_Ahi, p_Alo, NNODES, 80, 128);

    const int Kpad[3] = {128, 256, 256};
    const __nv_bfloat16* Boff_hi[3] = {p_Bhi + OFF_W0, p_Bhi + OFF_W1, p_Bhi + OFF_W2};
    const __nv_bfloat16* Boff_lo[3] = {p_Blo + OFF_W0, p_Blo + OFF_W1, p_Blo + OFF_W2};

    for (int L = 0; L < 3; L++) {
        // h = A @ W (fp32 out) + fused attention logits
        gemm_mma<<<dim3(NNODES / 128, 1), 512, GEMM_SMEM>>>(
            p_Ahi, p_Alo, Kpad[L], Boff_hi[L], Boff_lo[L],
            p_h, 256, 256, nullptr, nullptr, 0,
            nullptr, 0, aS[L], aD[L], p_als, p_ald);
        // fused softmax-aggregate; writes next layer's A (bf16 hi/lo)
        int act = (L < 2) ? 1 : 0;
        gat_agg<<<NNODES / 8, 256>>>(p_off, p_srcarr,
                                     (const float4*)p_als, (const float4*)p_ald,
                                     p_h, bb[L], act, p_Ahi, p_Alo);
    }

    // rot = h @ fc_w + fc_b -> d_out[0 : N*80]
    float* rot = (float*)d_out;
    gemm_mma<<<dim3(NNODES / 128, 1), 512, GEMM_SMEM>>>(
        p_Ahi, p_Alo, 256, p_Bhi + OFF_FC, p_Blo + OFF_FC,
        rot, 80, 80, nullptr, nullptr, 0,
        fc_b, 0, nullptr, nullptr, nullptr, nullptr);

    // root MLP
    conv_A_kernel<<<(4096 * 64 + 255) / 256, 256>>>(root, p_rAh, p_rAl, 4096, 60, 64);
    gemm_mma<<<dim3(32, 2), 512, GEMM_SMEM>>>(
        p_rAh, p_rAl, 64, p_Bhi + OFF_R1, p_Blo + OFF_R1,
        nullptr, 512, 0, p_r1h, p_r1l, 512,
        r_b1, 1, nullptr, nullptr, nullptr, nullptr);
    gemm_mma<<<dim3(32, 2), 512, GEMM_SMEM>>>(
        p_r1h, p_r1l, 512, p_Bhi + OFF_R2, p_Blo + OFF_R2,
        nullptr, 512, 0, p_r2h, p_r2l, 512,
        r_b2, 1, nullptr, nullptr, nullptr, nullptr);
    float* root_out = rot + (size_t)NNODES * 80;
    gemm_mma<<<dim3(32, 1), 512, GEMM_SMEM>>>(
        p_r2h, p_r2l, 512, p_Bhi + OFF_R3, p_Blo + OFF_R3,
        root_out, 60, 60, nullptr, nullptr, 0,
        r_b3, 0, nullptr, nullptr, nullptr, nullptr);
}